// round 16
// baseline (speedup 1.0000x reference)
#include <cuda_runtime.h>
#include <math.h>

#define NN   100000
#define EE   500000
#define SLOPE 0.01f
typedef unsigned long long ull;

// ---------------- scratch ----------------
__device__ float g_FS [2 * NN * 96];   // rel0, rel1 source projections
__device__ float g_RES[2 * NN * 96];
__device__ float g_EL [2 * NN * 3];
__device__ float g_ER [2 * NN * 3];
__device__ float g_EREC[2 * EE * 4];   // packed edge records {src_as_float, e0, e1, e2}
__device__ float g_GU [NN * 96];
__device__ float g_GI [NN * 96];
__device__ float g_HU [NN * 32];
__device__ float g_HI [NN * 32];
__device__ float g_WR [4 * 64 * 3];
// joint CSR over 2 relations (0=go dst=item, 1=back dst=user)
__device__ int g_deg [2 * NN];         // statically zero; re-zeroed by final launch each call
__device__ int g_off [2 * NN];
__device__ int g_cur [2 * NN];
__device__ int2 g_epair[2 * EE];       // {src, joint dst}
__device__ int g_bsum[256];

// ---------------- f32x2 helpers ----------------
__device__ __forceinline__ ull pack2(float x, float y) {
    ull r; asm("mov.b64 %0, {%1, %2};" : "=l"(r) : "f"(x), "f"(y)); return r;
}
__device__ __forceinline__ void ffma2(ull& d, ull a, ull b) {
    asm("fma.rn.f32x2 %0, %1, %2, %0;" : "+l"(d) : "l"(a), "l"(b));
}
__device__ __forceinline__ void unpack2(float& x, float& y, ull v) {
    asm("mov.b64 {%0, %1}, %2;" : "=f"(x), "=f"(y) : "l"(v));
}

// ---------------- WR section ----------------
__device__ __forceinline__ void wr_section(const float* W0, const float* W1,
                                           const float* attn, float* WR, int K, int i) {
    if (i >= 4 * K * 3) return;
    int c = i / (K * 3);
    int rem = i - c * K * 3;
    int k = rem / 3, h = rem - k * 3;
    const float* W = (c < 2) ? W0 : W1;
    const float* a = attn + c * 96 + h * 32;
    const float* wrow = W + k * 96 + h * 32;
    float s = 0.f;
    #pragma unroll
    for (int d = 0; d < 32; d++) s += wrow[d] * a[d];
    WR[i] = s;
}

// ---------------- launch 1: degree count (both rels) + WR layer1 ----------------
__global__ void pre_kernel(const int* __restrict__ d0, const int* __restrict__ d1,
                           int* __restrict__ deg,
                           const float* __restrict__ W0, const float* __restrict__ W1,
                           const float* __restrict__ attn, float* __restrict__ WR, int ne) {
    int i = blockIdx.x * 256 + threadIdx.x;
    if (blockIdx.y == 0) {
        if (i < ne) atomicAdd(&deg[d0[i]], 1);
    } else if (blockIdx.y == 1) {
        if (i < ne) atomicAdd(&deg[NN + d1[i]], 1);
    } else {
        wr_section(W0, W1, attn, WR, 64, i);
    }
}

// ---------------- quad GEMM + fused attn-score tail (proven) ----------------
// tile 64 rows x 96 cols; block (24,8)=192 thr; thread = 4 rowpairs x 4 cols (f32x2)
template <int K>
__global__ void gemm96_quad_kernel(const float* __restrict__ Xa, const float* __restrict__ Wa,
                                   float* __restrict__ Oa,
                                   const float* __restrict__ Xb, const float* __restrict__ Wb,
                                   float* __restrict__ Ob,
                                   const float* __restrict__ Xc, const float* __restrict__ Wc,
                                   float* __restrict__ Oc,
                                   const float* __restrict__ Xd, const float* __restrict__ Wd,
                                   float* __restrict__ Od,
                                   const float* __restrict__ WR4,
                                   float* __restrict__ S0, float* __restrict__ S1,
                                   float* __restrict__ S2, float* __restrict__ S3, int N) {
    const float* X; const float* W; float* O; float* S;
    switch (blockIdx.y) {
        case 0: X = Xa; W = Wa; O = Oa; S = S0; break;
        case 1: X = Xb; W = Wb; O = Ob; S = S1; break;
        case 2: X = Xc; W = Wc; O = Oc; S = S2; break;
        default: X = Xd; W = Wd; O = Od; S = S3; break;
    }
    __shared__ __align__(16) float sW[K * 96];
    __shared__ __align__(8) ull sXp[K][33];
    __shared__ float wrS[K * 3];
    const int t = threadIdx.y * 24 + threadIdx.x;
    const int row0 = blockIdx.x * 64;

    for (int i = t; i < K * 96; i += 192) sW[i] = W[i];
    for (int i = t; i < K * 3; i += 192) wrS[i] = WR4[blockIdx.y * K * 3 + i];
    float* sXf = (float*)sXp;
    for (int i = t; i < 64 * K; i += 192) {
        int r = i / K, k = i - r * K;
        int gr = row0 + r;
        sXf[k * 66 + r] = (gr < N) ? X[(size_t)gr * K + k] : 0.f;
    }
    __syncthreads();

    const int cg = threadIdx.x;
    const int rg = threadIdx.y;
    ull acc[4][4];
    #pragma unroll
    for (int a = 0; a < 4; a++)
        #pragma unroll
        for (int b = 0; b < 4; b++) acc[a][b] = 0ull;

    #pragma unroll 8
    for (int k = 0; k < K; k++) {
        float4 w = *reinterpret_cast<const float4*>(&sW[k * 96 + cg * 4]);
        ull w0 = pack2(w.x, w.x), w1 = pack2(w.y, w.y);
        ull w2 = pack2(w.z, w.z), w3 = pack2(w.w, w.w);
        #pragma unroll
        for (int rp = 0; rp < 4; rp++) {
            ull xp = sXp[k][rg * 4 + rp];
            ffma2(acc[rp][0], xp, w0);
            ffma2(acc[rp][1], xp, w1);
            ffma2(acc[rp][2], xp, w2);
            ffma2(acc[rp][3], xp, w3);
        }
    }
    #pragma unroll
    for (int rp = 0; rp < 4; rp++) {
        int row = row0 + (rg * 4 + rp) * 2;
        float lo0, hi0, lo1, hi1, lo2, hi2, lo3, hi3;
        unpack2(lo0, hi0, acc[rp][0]); unpack2(lo1, hi1, acc[rp][1]);
        unpack2(lo2, hi2, acc[rp][2]); unpack2(lo3, hi3, acc[rp][3]);
        if (row < N)
            *reinterpret_cast<float4*>(&O[(size_t)row * 96 + cg * 4]) =
                make_float4(lo0, lo1, lo2, lo3);
        if (row + 1 < N)
            *reinterpret_cast<float4*>(&O[(size_t)(row + 1) * 96 + cg * 4]) =
                make_float4(hi0, hi1, hi2, hi3);
    }

    if (t < 64) {
        int gr = row0 + t;
        if (gr < N) {
            float s0 = 0.f, s1 = 0.f, s2 = 0.f;
            #pragma unroll 8
            for (int k = 0; k < K; k++) {
                float xv = sXf[k * 66 + t];
                s0 = fmaf(xv, wrS[k * 3 + 0], s0);
                s1 = fmaf(xv, wrS[k * 3 + 1], s1);
                s2 = fmaf(xv, wrS[k * 3 + 2], s2);
            }
            S[gr * 3 + 0] = s0;
            S[gr * 3 + 1] = s1;
            S[gr * 3 + 2] = s2;
        }
    }
}

// ---------------- CSR scan ----------------
__global__ void scan1_kernel(const int* __restrict__ in, int* __restrict__ out,
                             int* __restrict__ bsum, int n) {
    __shared__ int sh[1024];
    int i = blockIdx.x * 1024 + threadIdx.x;
    int v = (i < n) ? in[i] : 0;
    sh[threadIdx.x] = v; __syncthreads();
    for (int ofs = 1; ofs < 1024; ofs <<= 1) {
        int tv = (threadIdx.x >= ofs) ? sh[threadIdx.x - ofs] : 0;
        __syncthreads();
        sh[threadIdx.x] += tv;
        __syncthreads();
    }
    if (i < n) out[i] = sh[threadIdx.x] - v;   // exclusive within tile
    if (threadIdx.x == 1023) bsum[blockIdx.x] = sh[1023];
}
// scan3 with fused block-prefix
__global__ void scan3_fused_kernel(int* __restrict__ off, const int* __restrict__ bsum,
                                   int* __restrict__ cur, int n, int nb) {
    __shared__ int sh[256];
    const int t = threadIdx.x;
    if (t < 256) sh[t] = (t < blockIdx.x && t < nb) ? bsum[t] : 0;
    __syncthreads();
    for (int ofs = 128; ofs > 0; ofs >>= 1) {
        if (t < ofs) sh[t] += sh[t + ofs];
        __syncthreads();
    }
    const int prefix = sh[0];
    int i = blockIdx.x * 1024 + t;
    if (i < n) { int v = off[i] + prefix; off[i] = v; cur[i] = v; }
}

// ---------------- scatter + fused layer-1 edge records ----------------
__global__ void scatter_rec_dual_kernel(const int* __restrict__ s0, const int* __restrict__ d0,
                                        const int* __restrict__ s1, const int* __restrict__ d1,
                                        int* __restrict__ cur, int2* __restrict__ epair,
                                        const float* __restrict__ el, const float* __restrict__ er,
                                        float4* __restrict__ rec, int ne) {
    int e = blockIdx.x * blockDim.x + threadIdx.x;
    if (e >= ne) return;
    int src, dj, relBase;
    if (blockIdx.y == 0) { src = s0[e]; dj = d0[e];      relBase = 0; }
    else                 { src = s1[e]; dj = NN + d1[e]; relBase = NN * 3; }
    int p = atomicAdd(&cur[dj], 1);
    epair[p] = make_int2(src, dj);
    float ex[3];
    #pragma unroll
    for (int h = 0; h < 3; h++) {
        float v = el[relBase + src * 3 + h] + er[dj * 3 + h];
        v = v > 0.f ? v : SLOPE * v;
        ex[h] = __expf(v);
    }
    rec[p] = make_float4(__int_as_float(src), ex[0], ex[1], ex[2]);
}

// ---------------- edge-parallel records (layer 2) ----------------
__global__ void edge_rec_kernel(const int2* __restrict__ epair,
                                const float* __restrict__ el, const float* __restrict__ er,
                                float4* __restrict__ rec, int ne2) {
    int i = blockIdx.x * blockDim.x + threadIdx.x;
    if (i >= ne2) return;
    int2 sd = __ldcs(epair + i);
    int s = sd.x, dj = sd.y;
    int relBase = (dj >= NN) ? NN * 3 : 0;
    float e[3];
    #pragma unroll
    for (int h = 0; h < 3; h++) {
        float v = el[relBase + s * 3 + h] + er[dj * 3 + h];
        v = v > 0.f ? v : SLOPE * v;
        e[h] = __expf(v);
    }
    rec[i] = make_float4(__int_as_float(s), e[0], e[1], e[2]);
}

// ---------------- GAT gather: warp per node, software-pipelined rec prefetch ----------------
__global__ void gat_gather6_kernel(const float4* __restrict__ rec, const int* __restrict__ off,
                                   const float* __restrict__ fs, const float* __restrict__ res,
                                   const float* __restrict__ bias0, const float* __restrict__ bias1,
                                   float* __restrict__ out0, float* __restrict__ out1,
                                   int totalE) {
    int w = (blockIdx.x * blockDim.x + threadIdx.x) >> 5;   // joint node index
    int lane = threadIdx.x & 31;
    if (w >= 2 * NN) return;
    const int rel  = (w >= NN);
    const int node = w - rel * NN;
    const float* FSr = fs + (size_t)rel * NN * 96 + lane;
    const float* RSr = res + (size_t)rel * NN * 96;
    const float* bias = rel ? bias1 : bias0;
    float* out = rel ? out1 : out0;

    int beg = off[w];
    int end = (w + 1 < 2 * NN) ? off[w + 1] : totalE;

    float a0 = 0.f, a1 = 0.f, a2 = 0.f, d0 = 0.f, d1 = 0.f, d2 = 0.f;

    int p = beg;
    bool ok0 = p < end, ok1 = p + 1 < end;
    float4 r0 = __ldcs(rec + (ok0 ? p : 0));
    float4 r1 = __ldcs(rec + (ok1 ? p + 1 : 0));
    while (p < end) {
        // prefetch next pair (clamped to index 0 when OOB; weights predicated to 0)
        int np = p + 2;
        bool nok0 = np < end, nok1 = np + 1 < end;
        float4 n0 = __ldcs(rec + (nok0 ? np : 0));
        float4 n1 = __ldcs(rec + (nok1 ? np + 1 : 0));
        // process current pair
        float e00 = ok0 ? r0.y : 0.f, e01 = ok0 ? r0.z : 0.f, e02 = ok0 ? r0.w : 0.f;
        float e10 = ok1 ? r1.y : 0.f, e11 = ok1 ? r1.z : 0.f, e12 = ok1 ? r1.w : 0.f;
        const float* f0 = FSr + (size_t)__float_as_int(r0.x) * 96;
        const float* f1 = FSr + (size_t)__float_as_int(r1.x) * 96;
        float v00 = f0[0], v01 = f0[32], v02 = f0[64];
        float v10 = f1[0], v11 = f1[32], v12 = f1[64];
        a0 = fmaf(e00, v00, a0); a1 = fmaf(e01, v01, a1); a2 = fmaf(e02, v02, a2);
        a0 = fmaf(e10, v10, a0); a1 = fmaf(e11, v11, a1); a2 = fmaf(e12, v12, a2);
        d0 += e00 + e10; d1 += e01 + e11; d2 += e02 + e12;
        r0 = n0; r1 = n1; ok0 = nok0; ok1 = nok1; p = np;
    }
    size_t o = (size_t)node * 96 + lane;
    out[o]      = (d0 > 0.f ? a0 / d0 : 0.f) + __ldcs(RSr + o)      + bias[lane];
    out[o + 32] = (d1 > 0.f ? a1 / d1 : 0.f) + __ldcs(RSr + o + 32) + bias[lane + 32];
    out[o + 64] = (d2 > 0.f ? a2 / d2 : 0.f) + __ldcs(RSr + o + 64) + bias[lane + 64];
}

// ---------------- dual Linear(96->32) + BN(eval) + ReLU + EXTRA section ----------------
// EXTRA: 1 = WR for layer 2 (y==2), 2 = zero DEG for next call (y==2)
template <int EXTRA>
__global__ void lin_bn_relu_dual_kernel(const float* __restrict__ in0, const float* __restrict__ in1,
                                        const float* __restrict__ Wb, const float* __restrict__ bb,
                                        const float* __restrict__ bnb,
                                        float* __restrict__ out0, float* __restrict__ out1,
                                        const float* __restrict__ nW0, const float* __restrict__ nW1,
                                        const float* __restrict__ nattn, float* __restrict__ WRout,
                                        int* __restrict__ deg, int n) {
    const int t = threadIdx.x;  // 256
    if (blockIdx.y == 2) {
        int i = blockIdx.x * 256 + t;
        if (EXTRA == 1) {
            wr_section(nW0, nW1, nattn, WRout, 32, i);
        } else if (EXTRA == 2) {
            if (i < 2 * NN) deg[i] = 0;
        }
        return;
    }
    const float* in  = blockIdx.y ? in1 : in0;
    const float* W   = Wb  + (blockIdx.y ? 96 * 32 : 0);
    const float* b   = bb  + (blockIdx.y ? 32 : 0);
    const float* bn  = bnb + (blockIdx.y ? 128 : 0);
    float*       out = blockIdx.y ? out1 : out0;

    __shared__ float sW[96 * 32];
    __shared__ float sIn[32][97];
    __shared__ float sScale[32], sShift[32];

    const float4* W4 = reinterpret_cast<const float4*>(W);
    for (int i = t; i < 96 * 32 / 4; i += 256)
        *reinterpret_cast<float4*>(&sW[i * 4]) = W4[i];
    if (t < 32) {
        float gamma = bn[t], beta = bn[32 + t], mean = bn[64 + t], var = bn[96 + t];
        float sc = gamma * rsqrtf(var + 1e-5f);
        sScale[t] = sc;
        sShift[t] = beta + (b[t] - mean) * sc;
    }
    const int node0 = blockIdx.x * 32;
    const float4* in4 = reinterpret_cast<const float4*>(in);
    for (int i = t; i < 32 * 24; i += 256) {
        int r = i / 24, f = i - r * 24;
        int gn = node0 + r;
        float4 v = (gn < n) ? in4[(size_t)gn * 24 + f] : make_float4(0.f, 0.f, 0.f, 0.f);
        sIn[r][f * 4 + 0] = v.x; sIn[r][f * 4 + 1] = v.y;
        sIn[r][f * 4 + 2] = v.z; sIn[r][f * 4 + 3] = v.w;
    }
    __syncthreads();

    const int c = t & 31, ng = t >> 5;
    float acc[4] = {0.f, 0.f, 0.f, 0.f};
    #pragma unroll 8
    for (int k = 0; k < 96; k++) {
        float wv = sW[k * 32 + c];
        #pragma unroll
        for (int r = 0; r < 4; r++) acc[r] = fmaf(sIn[ng * 4 + r][k], wv, acc[r]);
    }
    #pragma unroll
    for (int r = 0; r < 4; r++) {
        int gn = node0 + ng * 4 + r;
        if (gn < n) {
            float y = acc[r] * sScale[c] + sShift[c];
            out[(size_t)gn * 32 + c] = y > 0.f ? y : 0.f;
        }
    }
}

// ==================================================================================
extern "C" void kernel_launch(void* const* d_in, const int* in_sizes, int n_in,
                              void* d_out, int out_size) {
    const float* emb_user = (const float*)d_in[0];
    const float* emb_item = (const float*)d_in[1];
    const float* W1    = (const float*)d_in[2];
    const float* attn1 = (const float*)d_in[3];
    const float* res1  = (const float*)d_in[4];
    const float* bias1 = (const float*)d_in[5];
    const float* nnW1  = (const float*)d_in[6];
    const float* nnb1  = (const float*)d_in[7];
    const float* bn1   = (const float*)d_in[8];
    const float* W2    = (const float*)d_in[9];
    const float* attn2 = (const float*)d_in[10];
    const float* res2  = (const float*)d_in[11];
    const float* bias2 = (const float*)d_in[12];
    const float* nnW2  = (const float*)d_in[13];
    const float* nnb2  = (const float*)d_in[14];
    const float* bn2   = (const float*)d_in[15];
    const int* go_src   = (const int*)d_in[16];
    const int* go_dst   = (const int*)d_in[17];
    const int* back_src = (const int*)d_in[18];
    const int* back_dst = (const int*)d_in[19];
    const int E = in_sizes[16];
    const int N = NN;

    float *FS, *RES, *EL, *ER, *GU, *GI, *HU, *HI, *WR;
    float4* EREC;
    int2* EPAIR;
    int *DEG, *OFF, *CUR, *BSUM;
    cudaGetSymbolAddress((void**)&FS,    g_FS);
    cudaGetSymbolAddress((void**)&RES,   g_RES);
    cudaGetSymbolAddress((void**)&EL,    g_EL);
    cudaGetSymbolAddress((void**)&ER,    g_ER);
    cudaGetSymbolAddress((void**)&EREC,  g_EREC);
    cudaGetSymbolAddress((void**)&GU,    g_GU);
    cudaGetSymbolAddress((void**)&GI,    g_GI);
    cudaGetSymbolAddress((void**)&HU,    g_HU);
    cudaGetSymbolAddress((void**)&HI,    g_HI);
    cudaGetSymbolAddress((void**)&WR,    g_WR);
    cudaGetSymbolAddress((void**)&DEG,   g_deg);
    cudaGetSymbolAddress((void**)&OFF,   g_off);
    cudaGetSymbolAddress((void**)&CUR,   g_cur);
    cudaGetSymbolAddress((void**)&EPAIR, g_epair);
    cudaGetSymbolAddress((void**)&BSUM,  g_bsum);

    const int NB2 = (2 * N + 1023) / 1024;   // 196
    const int eb = (E + 255) / 256;
    const int eb2 = (2 * E + 255) / 256;
    const int gemmBlocks = (N + 63) / 64;
    const int gatherBlocks = (2 * N * 32 + 255) / 256;   // warp per node
    const int lbBlocks = (N + 31) / 32;

    // 1-3: count + WR layer1; scan phase 1; scan finalize (fused block-prefix)
    pre_kernel<<<dim3(eb, 3), 256>>>(go_dst, back_dst, DEG, W1, W1 + 64 * 96, attn1, WR, E);
    scan1_kernel<<<NB2, 1024>>>(DEG, OFF, BSUM, 2 * N);
    scan3_fused_kernel<<<NB2, 1024>>>(OFF, BSUM, CUR, 2 * N, NB2);

    // 4 (PROFILED): layer-1 GEMM quad + fused attn scores
    gemm96_quad_kernel<64><<<dim3(gemmBlocks, 4), dim3(24, 8)>>>(
        emb_user, W1,             FS,
        emb_item, res1,           RES,
        emb_item, W1 + 64 * 96,   FS + (size_t)N * 96,
        emb_user, res1 + 64 * 96, RES + (size_t)N * 96,
        WR, EL, ER, EL + N * 3, ER + N * 3, N);

    // 5: scatter + layer-1 edge records (EL/ER ready)
    scatter_rec_dual_kernel<<<dim3(eb, 2), 256>>>(go_src, go_dst, back_src, back_dst,
                                                  CUR, EPAIR, EL, ER, EREC, E);

    // 6-7: layer-1 gather + MLP (+ WR layer2 section)
    gat_gather6_kernel<<<gatherBlocks, 256>>>(EREC, OFF, FS, RES,
                                              bias1, bias1 + 96, GI, GU, 2 * E);
    lin_bn_relu_dual_kernel<1><<<dim3(lbBlocks, 3), 256>>>(GU, GI, nnW1, nnb1, bn1, HU, HI,
                                                           W2, W2 + 32 * 96, attn2, WR,
                                                           DEG, N);

    // 8-10: layer 2
    gemm96_quad_kernel<32><<<dim3(gemmBlocks, 4), dim3(24, 8)>>>(
        HU, W2,             FS,
        HI, res2,           RES,
        HI, W2 + 32 * 96,   FS + (size_t)N * 96,
        HU, res2 + 32 * 96, RES + (size_t)N * 96,
        WR, EL, ER, EL + N * 3, ER + N * 3, N);
    edge_rec_kernel<<<eb2, 256>>>(EPAIR, EL, ER, EREC, 2 * E);
    gat_gather6_kernel<<<gatherBlocks, 256>>>(EREC, OFF, FS, RES,
                                              bias2, bias2 + 96, GI, GU, 2 * E);

    // 11: output MLPs + zero DEG for next call
    float* out = (float*)d_out;
    lin_bn_relu_dual_kernel<2><<<dim3(lbBlocks, 3), 256>>>(GU, GI, nnW2, nnb2, bn2,
                                                           out, out + (size_t)N * 32,
                                                           W2, W2, attn2, WR,
                                                           DEG, N);
}

// round 17
// speedup vs baseline: 1.0830x; 1.0830x over previous
#include <cuda_runtime.h>
#include <math.h>

#define NN   100000
#define EE   500000
#define SLOPE 0.01f
typedef unsigned long long ull;

// ---------------- scratch ----------------
__device__ float g_FS [2 * NN * 96];   // rel0, rel1 source projections
__device__ float g_RES[2 * NN * 96];
__device__ float g_EL [2 * NN * 3];
__device__ float g_ER [2 * NN * 3];
__device__ float g_EREC[2 * EE * 4];   // packed edge records {src_as_float, e0, e1, e2}
__device__ float g_GU [NN * 96];
__device__ float g_GI [NN * 96];
__device__ float g_HU [NN * 32];
__device__ float g_HI [NN * 32];
__device__ float g_WR [4 * 64 * 3];
// joint CSR over 2 relations (0=go dst=item, 1=back dst=user)
__device__ int g_deg [2 * NN];         // statically zero; re-zeroed by final launch each call
__device__ int g_off [2 * NN];
__device__ int g_cur [2 * NN];
__device__ int2 g_epair[2 * EE];       // {src, joint dst}
__device__ int g_bsum[256];

// ---------------- f32x2 helpers ----------------
__device__ __forceinline__ ull pack2(float x, float y) {
    ull r; asm("mov.b64 %0, {%1, %2};" : "=l"(r) : "f"(x), "f"(y)); return r;
}
__device__ __forceinline__ void ffma2(ull& d, ull a, ull b) {
    asm("fma.rn.f32x2 %0, %1, %2, %0;" : "+l"(d) : "l"(a), "l"(b));
}
__device__ __forceinline__ void unpack2(float& x, float& y, ull v) {
    asm("mov.b64 {%0, %1}, %2;" : "=f"(x), "=f"(y) : "l"(v));
}

// ---------------- WR section ----------------
__device__ __forceinline__ void wr_section(const float* W0, const float* W1,
                                           const float* attn, float* WR, int K, int i) {
    if (i >= 4 * K * 3) return;
    int c = i / (K * 3);
    int rem = i - c * K * 3;
    int k = rem / 3, h = rem - k * 3;
    const float* W = (c < 2) ? W0 : W1;
    const float* a = attn + c * 96 + h * 32;
    const float* wrow = W + k * 96 + h * 32;
    float s = 0.f;
    #pragma unroll
    for (int d = 0; d < 32; d++) s += wrow[d] * a[d];
    WR[i] = s;
}

// ---------------- launch 1: degree count (both rels) + WR layer1 ----------------
__global__ void pre_kernel(const int* __restrict__ d0, const int* __restrict__ d1,
                           int* __restrict__ deg,
                           const float* __restrict__ W0, const float* __restrict__ W1,
                           const float* __restrict__ attn, float* __restrict__ WR, int ne) {
    int i = blockIdx.x * 256 + threadIdx.x;
    if (blockIdx.y == 0) {
        if (i < ne) atomicAdd(&deg[d0[i]], 1);
    } else if (blockIdx.y == 1) {
        if (i < ne) atomicAdd(&deg[NN + d1[i]], 1);
    } else {
        wr_section(W0, W1, attn, WR, 64, i);
    }
}

// ---------------- quad GEMM + fused attn-score tail (proven) ----------------
// tile 64 rows x 96 cols; block (24,8)=192 thr; thread = 4 rowpairs x 4 cols (f32x2)
template <int K>
__global__ void gemm96_quad_kernel(const float* __restrict__ Xa, const float* __restrict__ Wa,
                                   float* __restrict__ Oa,
                                   const float* __restrict__ Xb, const float* __restrict__ Wb,
                                   float* __restrict__ Ob,
                                   const float* __restrict__ Xc, const float* __restrict__ Wc,
                                   float* __restrict__ Oc,
                                   const float* __restrict__ Xd, const float* __restrict__ Wd,
                                   float* __restrict__ Od,
                                   const float* __restrict__ WR4,
                                   float* __restrict__ S0, float* __restrict__ S1,
                                   float* __restrict__ S2, float* __restrict__ S3, int N) {
    const float* X; const float* W; float* O; float* S;
    switch (blockIdx.y) {
        case 0: X = Xa; W = Wa; O = Oa; S = S0; break;
        case 1: X = Xb; W = Wb; O = Ob; S = S1; break;
        case 2: X = Xc; W = Wc; O = Oc; S = S2; break;
        default: X = Xd; W = Wd; O = Od; S = S3; break;
    }
    __shared__ __align__(16) float sW[K * 96];
    __shared__ __align__(8) ull sXp[K][33];
    __shared__ float wrS[K * 3];
    const int t = threadIdx.y * 24 + threadIdx.x;
    const int row0 = blockIdx.x * 64;

    for (int i = t; i < K * 96; i += 192) sW[i] = W[i];
    for (int i = t; i < K * 3; i += 192) wrS[i] = WR4[blockIdx.y * K * 3 + i];
    float* sXf = (float*)sXp;
    for (int i = t; i < 64 * K; i += 192) {
        int r = i / K, k = i - r * K;
        int gr = row0 + r;
        sXf[k * 66 + r] = (gr < N) ? X[(size_t)gr * K + k] : 0.f;
    }
    __syncthreads();

    const int cg = threadIdx.x;
    const int rg = threadIdx.y;
    ull acc[4][4];
    #pragma unroll
    for (int a = 0; a < 4; a++)
        #pragma unroll
        for (int b = 0; b < 4; b++) acc[a][b] = 0ull;

    #pragma unroll 8
    for (int k = 0; k < K; k++) {
        float4 w = *reinterpret_cast<const float4*>(&sW[k * 96 + cg * 4]);
        ull w0 = pack2(w.x, w.x), w1 = pack2(w.y, w.y);
        ull w2 = pack2(w.z, w.z), w3 = pack2(w.w, w.w);
        #pragma unroll
        for (int rp = 0; rp < 4; rp++) {
            ull xp = sXp[k][rg * 4 + rp];
            ffma2(acc[rp][0], xp, w0);
            ffma2(acc[rp][1], xp, w1);
            ffma2(acc[rp][2], xp, w2);
            ffma2(acc[rp][3], xp, w3);
        }
    }
    #pragma unroll
    for (int rp = 0; rp < 4; rp++) {
        int row = row0 + (rg * 4 + rp) * 2;
        float lo0, hi0, lo1, hi1, lo2, hi2, lo3, hi3;
        unpack2(lo0, hi0, acc[rp][0]); unpack2(lo1, hi1, acc[rp][1]);
        unpack2(lo2, hi2, acc[rp][2]); unpack2(lo3, hi3, acc[rp][3]);
        if (row < N)
            *reinterpret_cast<float4*>(&O[(size_t)row * 96 + cg * 4]) =
                make_float4(lo0, lo1, lo2, lo3);
        if (row + 1 < N)
            *reinterpret_cast<float4*>(&O[(size_t)(row + 1) * 96 + cg * 4]) =
                make_float4(hi0, hi1, hi2, hi3);
    }

    if (t < 64) {
        int gr = row0 + t;
        if (gr < N) {
            float s0 = 0.f, s1 = 0.f, s2 = 0.f;
            #pragma unroll 8
            for (int k = 0; k < K; k++) {
                float xv = sXf[k * 66 + t];
                s0 = fmaf(xv, wrS[k * 3 + 0], s0);
                s1 = fmaf(xv, wrS[k * 3 + 1], s1);
                s2 = fmaf(xv, wrS[k * 3 + 2], s2);
            }
            S[gr * 3 + 0] = s0;
            S[gr * 3 + 1] = s1;
            S[gr * 3 + 2] = s2;
        }
    }
}

// ---------------- CSR scan ----------------
__global__ void scan1_kernel(const int* __restrict__ in, int* __restrict__ out,
                             int* __restrict__ bsum, int n) {
    __shared__ int sh[1024];
    int i = blockIdx.x * 1024 + threadIdx.x;
    int v = (i < n) ? in[i] : 0;
    sh[threadIdx.x] = v; __syncthreads();
    for (int ofs = 1; ofs < 1024; ofs <<= 1) {
        int tv = (threadIdx.x >= ofs) ? sh[threadIdx.x - ofs] : 0;
        __syncthreads();
        sh[threadIdx.x] += tv;
        __syncthreads();
    }
    if (i < n) out[i] = sh[threadIdx.x] - v;   // exclusive within tile
    if (threadIdx.x == 1023) bsum[blockIdx.x] = sh[1023];
}
// scan3 with fused block-prefix
__global__ void scan3_fused_kernel(int* __restrict__ off, const int* __restrict__ bsum,
                                   int* __restrict__ cur, int n, int nb) {
    __shared__ int sh[256];
    const int t = threadIdx.x;
    if (t < 256) sh[t] = (t < blockIdx.x && t < nb) ? bsum[t] : 0;
    __syncthreads();
    for (int ofs = 128; ofs > 0; ofs >>= 1) {
        if (t < ofs) sh[t] += sh[t + ofs];
        __syncthreads();
    }
    const int prefix = sh[0];
    int i = blockIdx.x * 1024 + t;
    if (i < n) { int v = off[i] + prefix; off[i] = v; cur[i] = v; }
}

// ---------------- scatter + fused layer-1 edge records ----------------
__global__ void scatter_rec_dual_kernel(const int* __restrict__ s0, const int* __restrict__ d0,
                                        const int* __restrict__ s1, const int* __restrict__ d1,
                                        int* __restrict__ cur, int2* __restrict__ epair,
                                        const float* __restrict__ el, const float* __restrict__ er,
                                        float4* __restrict__ rec, int ne) {
    int e = blockIdx.x * blockDim.x + threadIdx.x;
    if (e >= ne) return;
    int src, dj, relBase;
    if (blockIdx.y == 0) { src = s0[e]; dj = d0[e];      relBase = 0; }
    else                 { src = s1[e]; dj = NN + d1[e]; relBase = NN * 3; }
    int p = atomicAdd(&cur[dj], 1);
    epair[p] = make_int2(src, dj);
    float ex[3];
    #pragma unroll
    for (int h = 0; h < 3; h++) {
        float v = el[relBase + src * 3 + h] + er[dj * 3 + h];
        v = v > 0.f ? v : SLOPE * v;
        ex[h] = __expf(v);
    }
    rec[p] = make_float4(__int_as_float(src), ex[0], ex[1], ex[2]);
}

// ---------------- edge-parallel records (layer 2) ----------------
__global__ void edge_rec_kernel(const int2* __restrict__ epair,
                                const float* __restrict__ el, const float* __restrict__ er,
                                float4* __restrict__ rec, int ne2) {
    int i = blockIdx.x * blockDim.x + threadIdx.x;
    if (i >= ne2) return;
    int2 sd = __ldcs(epair + i);
    int s = sd.x, dj = sd.y;
    int relBase = (dj >= NN) ? NN * 3 : 0;
    float e[3];
    #pragma unroll
    for (int h = 0; h < 3; h++) {
        float v = el[relBase + s * 3 + h] + er[dj * 3 + h];
        v = v > 0.f ? v : SLOPE * v;
        e[h] = __expf(v);
    }
    rec[i] = make_float4(__int_as_float(s), e[0], e[1], e[2]);
}

// ---------------- GAT gather: warp per node, all 3 heads per pass (R15-proven) ----------------
__global__ void gat_gather5_kernel(const float4* __restrict__ rec, const int* __restrict__ off,
                                   const float* __restrict__ fs, const float* __restrict__ res,
                                   const float* __restrict__ bias0, const float* __restrict__ bias1,
                                   float* __restrict__ out0, float* __restrict__ out1,
                                   int totalE) {
    int w = (blockIdx.x * blockDim.x + threadIdx.x) >> 5;   // joint node index
    int lane = threadIdx.x & 31;
    if (w >= 2 * NN) return;
    const int rel  = (w >= NN);
    const int node = w - rel * NN;
    const float* FSr = fs + (size_t)rel * NN * 96 + lane;
    const float* RSr = res + (size_t)rel * NN * 96;
    const float* bias = rel ? bias1 : bias0;
    float* out = rel ? out1 : out0;

    int beg = off[w];
    int end = (w + 1 < 2 * NN) ? off[w + 1] : totalE;

    float a0 = 0.f, a1 = 0.f, a2 = 0.f, d0 = 0.f, d1 = 0.f, d2 = 0.f;
    int p = beg;
    for (; p + 2 <= end; p += 2) {
        float4 r0 = __ldcs(rec + p);
        float4 r1 = __ldcs(rec + p + 1);
        const float* f0 = FSr + (size_t)__float_as_int(r0.x) * 96;
        const float* f1 = FSr + (size_t)__float_as_int(r1.x) * 96;
        float v00 = f0[0], v01 = f0[32], v02 = f0[64];
        float v10 = f1[0], v11 = f1[32], v12 = f1[64];
        a0 = fmaf(r0.y, v00, a0); a1 = fmaf(r0.z, v01, a1); a2 = fmaf(r0.w, v02, a2);
        a0 = fmaf(r1.y, v10, a0); a1 = fmaf(r1.z, v11, a1); a2 = fmaf(r1.w, v12, a2);
        d0 += r0.y + r1.y; d1 += r0.z + r1.z; d2 += r0.w + r1.w;
    }
    if (p < end) {
        float4 r0 = __ldcs(rec + p);
        const float* f0 = FSr + (size_t)__float_as_int(r0.x) * 96;
        a0 = fmaf(r0.y, f0[0], a0); a1 = fmaf(r0.z, f0[32], a1); a2 = fmaf(r0.w, f0[64], a2);
        d0 += r0.y; d1 += r0.z; d2 += r0.w;
    }
    size_t o = (size_t)node * 96 + lane;
    out[o]      = (d0 > 0.f ? a0 / d0 : 0.f) + __ldcs(RSr + o)      + bias[lane];
    out[o + 32] = (d1 > 0.f ? a1 / d1 : 0.f) + __ldcs(RSr + o + 32) + bias[lane + 32];
    out[o + 64] = (d2 > 0.f ? a2 / d2 : 0.f) + __ldcs(RSr + o + 64) + bias[lane + 64];
}

// ---------------- dual Linear(96->32) + BN(eval) + ReLU + EXTRA section ----------------
// EXTRA: 1 = WR for layer 2 (y==2), 2 = zero DEG for next call (y==2)
template <int EXTRA>
__global__ void lin_bn_relu_dual_kernel(const float* __restrict__ in0, const float* __restrict__ in1,
                                        const float* __restrict__ Wb, const float* __restrict__ bb,
                                        const float* __restrict__ bnb,
                                        float* __restrict__ out0, float* __restrict__ out1,
                                        const float* __restrict__ nW0, const float* __restrict__ nW1,
                                        const float* __restrict__ nattn, float* __restrict__ WRout,
                                        int* __restrict__ deg, int n) {
    const int t = threadIdx.x;  // 256
    if (blockIdx.y == 2) {
        int i = blockIdx.x * 256 + t;
        if (EXTRA == 1) {
            wr_section(nW0, nW1, nattn, WRout, 32, i);
        } else if (EXTRA == 2) {
            if (i < 2 * NN) deg[i] = 0;
        }
        return;
    }
    const float* in  = blockIdx.y ? in1 : in0;
    const float* W   = Wb  + (blockIdx.y ? 96 * 32 : 0);
    const float* b   = bb  + (blockIdx.y ? 32 : 0);
    const float* bn  = bnb + (blockIdx.y ? 128 : 0);
    float*       out = blockIdx.y ? out1 : out0;

    __shared__ float sW[96 * 32];
    __shared__ float sIn[32][97];
    __shared__ float sScale[32], sShift[32];

    const float4* W4 = reinterpret_cast<const float4*>(W);
    for (int i = t; i < 96 * 32 / 4; i += 256)
        *reinterpret_cast<float4*>(&sW[i * 4]) = W4[i];
    if (t < 32) {
        float gamma = bn[t], beta = bn[32 + t], mean = bn[64 + t], var = bn[96 + t];
        float sc = gamma * rsqrtf(var + 1e-5f);
        sScale[t] = sc;
        sShift[t] = beta + (b[t] - mean) * sc;
    }
    const int node0 = blockIdx.x * 32;
    const float4* in4 = reinterpret_cast<const float4*>(in);
    for (int i = t; i < 32 * 24; i += 256) {
        int r = i / 24, f = i - r * 24;
        int gn = node0 + r;
        float4 v = (gn < n) ? in4[(size_t)gn * 24 + f] : make_float4(0.f, 0.f, 0.f, 0.f);
        sIn[r][f * 4 + 0] = v.x; sIn[r][f * 4 + 1] = v.y;
        sIn[r][f * 4 + 2] = v.z; sIn[r][f * 4 + 3] = v.w;
    }
    __syncthreads();

    const int c = t & 31, ng = t >> 5;
    float acc[4] = {0.f, 0.f, 0.f, 0.f};
    #pragma unroll 8
    for (int k = 0; k < 96; k++) {
        float wv = sW[k * 32 + c];
        #pragma unroll
        for (int r = 0; r < 4; r++) acc[r] = fmaf(sIn[ng * 4 + r][k], wv, acc[r]);
    }
    #pragma unroll
    for (int r = 0; r < 4; r++) {
        int gn = node0 + ng * 4 + r;
        if (gn < n) {
            float y = acc[r] * sScale[c] + sShift[c];
            out[(size_t)gn * 32 + c] = y > 0.f ? y : 0.f;
        }
    }
}

// ==================================================================================
extern "C" void kernel_launch(void* const* d_in, const int* in_sizes, int n_in,
                              void* d_out, int out_size) {
    const float* emb_user = (const float*)d_in[0];
    const float* emb_item = (const float*)d_in[1];
    const float* W1    = (const float*)d_in[2];
    const float* attn1 = (const float*)d_in[3];
    const float* res1  = (const float*)d_in[4];
    const float* bias1 = (const float*)d_in[5];
    const float* nnW1  = (const float*)d_in[6];
    const float* nnb1  = (const float*)d_in[7];
    const float* bn1   = (const float*)d_in[8];
    const float* W2    = (const float*)d_in[9];
    const float* attn2 = (const float*)d_in[10];
    const float* res2  = (const float*)d_in[11];
    const float* bias2 = (const float*)d_in[12];
    const float* nnW2  = (const float*)d_in[13];
    const float* nnb2  = (const float*)d_in[14];
    const float* bn2   = (const float*)d_in[15];
    const int* go_src   = (const int*)d_in[16];
    const int* go_dst   = (const int*)d_in[17];
    const int* back_src = (const int*)d_in[18];
    const int* back_dst = (const int*)d_in[19];
    const int E = in_sizes[16];
    const int N = NN;

    float *FS, *RES, *EL, *ER, *GU, *GI, *HU, *HI, *WR;
    float4* EREC;
    int2* EPAIR;
    int *DEG, *OFF, *CUR, *BSUM;
    cudaGetSymbolAddress((void**)&FS,    g_FS);
    cudaGetSymbolAddress((void**)&RES,   g_RES);
    cudaGetSymbolAddress((void**)&EL,    g_EL);
    cudaGetSymbolAddress((void**)&ER,    g_ER);
    cudaGetSymbolAddress((void**)&EREC,  g_EREC);
    cudaGetSymbolAddress((void**)&GU,    g_GU);
    cudaGetSymbolAddress((void**)&GI,    g_GI);
    cudaGetSymbolAddress((void**)&HU,    g_HU);
    cudaGetSymbolAddress((void**)&HI,    g_HI);
    cudaGetSymbolAddress((void**)&WR,    g_WR);
    cudaGetSymbolAddress((void**)&DEG,   g_deg);
    cudaGetSymbolAddress((void**)&OFF,   g_off);
    cudaGetSymbolAddress((void**)&CUR,   g_cur);
    cudaGetSymbolAddress((void**)&EPAIR, g_epair);
    cudaGetSymbolAddress((void**)&BSUM,  g_bsum);

    const int NB2 = (2 * N + 1023) / 1024;   // 196
    const int eb = (E + 255) / 256;
    const int eb2 = (2 * E + 255) / 256;
    const int gemmBlocks = (N + 63) / 64;
    const int gatherBlocks = (2 * N * 32 + 127) / 128;   // warp per node, 128-thr blocks
    const int lbBlocks = (N + 31) / 32;

    // 1-3: count + WR layer1; scan phase 1; scan finalize (fused block-prefix)
    pre_kernel<<<dim3(eb, 3), 256>>>(go_dst, back_dst, DEG, W1, W1 + 64 * 96, attn1, WR, E);
    scan1_kernel<<<NB2, 1024>>>(DEG, OFF, BSUM, 2 * N);
    scan3_fused_kernel<<<NB2, 1024>>>(OFF, BSUM, CUR, 2 * N, NB2);

    // 4 (PROFILED): layer-1 GEMM quad + fused attn scores
    gemm96_quad_kernel<64><<<dim3(gemmBlocks, 4), dim3(24, 8)>>>(
        emb_user, W1,             FS,
        emb_item, res1,           RES,
        emb_item, W1 + 64 * 96,   FS + (size_t)N * 96,
        emb_user, res1 + 64 * 96, RES + (size_t)N * 96,
        WR, EL, ER, EL + N * 3, ER + N * 3, N);

    // 5: scatter + layer-1 edge records (EL/ER ready)
    scatter_rec_dual_kernel<<<dim3(eb, 2), 256>>>(go_src, go_dst, back_src, back_dst,
                                                  CUR, EPAIR, EL, ER, EREC, E);

    // 6-7: layer-1 gather + MLP (+ WR layer2 section)
    gat_gather5_kernel<<<gatherBlocks, 128>>>(EREC, OFF, FS, RES,
                                              bias1, bias1 + 96, GI, GU, 2 * E);
    lin_bn_relu_dual_kernel<1><<<dim3(lbBlocks, 3), 256>>>(GU, GI, nnW1, nnb1, bn1, HU, HI,
                                                           W2, W2 + 32 * 96, attn2, WR,
                                                           DEG, N);

    // 8-10: layer 2
    gemm96_quad_kernel<32><<<dim3(gemmBlocks, 4), dim3(24, 8)>>>(
        HU, W2,             FS,
        HI, res2,           RES,
        HI, W2 + 32 * 96,   FS + (size_t)N * 96,
        HU, res2 + 32 * 96, RES + (size_t)N * 96,
        WR, EL, ER, EL + N * 3, ER + N * 3, N);
    edge_rec_kernel<<<eb2, 256>>>(EPAIR, EL, ER, EREC, 2 * E);
    gat_gather5_kernel<<<gatherBlocks, 128>>>(EREC, OFF, FS, RES,
                                              bias2, bias2 + 96, GI, GU, 2 * E);

    // 11: output MLPs + zero DEG for next call
    float* out = (float*)d_out;
    lin_bn_relu_dual_kernel<2><<<dim3(lbBlocks, 3), 256>>>(GU, GI, nnW2, nnb2, bn2,
                                                           out, out + (size_t)N * 32,
                                                           W2, W2, attn2, WR,
                                                           DEG, N);
}